// round 1
// baseline (speedup 1.0000x reference)
#include <cuda_runtime.h>
#include <math.h>

#define S_LEN   2048
#define D_MODEL 4096
#define NQ      32
#define NKV     8
#define HD      128
#define WINDOW  1024

// ---------------- scratch (allocation-free rule: __device__ globals) -------
__device__ float g_Q[S_LEN * NQ * HD];     // 32 MB
__device__ float g_K[S_LEN * NKV * HD];    //  8 MB
__device__ float g_V[S_LEN * NKV * HD];    //  8 MB
__device__ float g_A[S_LEN * NQ * HD];     // 32 MB

// ---------------------------------------------------------------------------
// Generic fp32 GEMM: C[M,N] = A[M,K] @ B[K,N], row-major.
// M,N multiples of 128, K multiple of 16. 256 threads, 128x128 tile,
// 8x8 micro-tile per thread, BK=16, float4 global & smem traffic.
// ---------------------------------------------------------------------------
__global__ __launch_bounds__(256) void gemm_kernel(
    const float* __restrict__ A, const float* __restrict__ B,
    float* __restrict__ C, int M, int N, int K)
{
    __shared__ float As[16][132];   // transposed A tile, padded
    __shared__ float Bs[16][128];

    const int tid = threadIdx.x;
    const int tx = tid & 15;        // 0..15  -> column group
    const int ty = tid >> 4;        // 0..15  -> row group
    const int m0 = blockIdx.y * 128;
    const int n0 = blockIdx.x * 128;

    float acc[8][8];
#pragma unroll
    for (int i = 0; i < 8; i++)
#pragma unroll
        for (int j = 0; j < 8; j++) acc[i][j] = 0.f;

    const int arow = tid >> 2;            // 0..63
    const int acol = (tid & 3) * 4;       // 0,4,8,12
    const int brow = tid >> 5;            // 0..7
    const int bcol = (tid & 31) * 4;      // 0..124

    for (int k0 = 0; k0 < K; k0 += 16) {
        __syncthreads();
        // A tile 128x16 (two 64-row halves), stored transposed As[k][m]
        float4 av0 = *(const float4*)&A[(size_t)(m0 + arow) * K + k0 + acol];
        float4 av1 = *(const float4*)&A[(size_t)(m0 + arow + 64) * K + k0 + acol];
        As[acol + 0][arow] = av0.x;
        As[acol + 1][arow] = av0.y;
        As[acol + 2][arow] = av0.z;
        As[acol + 3][arow] = av0.w;
        As[acol + 0][arow + 64] = av1.x;
        As[acol + 1][arow + 64] = av1.y;
        As[acol + 2][arow + 64] = av1.z;
        As[acol + 3][arow + 64] = av1.w;
        // B tile 16x128
        *(float4*)&Bs[brow][bcol] =
            *(const float4*)&B[(size_t)(k0 + brow) * N + n0 + bcol];
        *(float4*)&Bs[brow + 8][bcol] =
            *(const float4*)&B[(size_t)(k0 + brow + 8) * N + n0 + bcol];
        __syncthreads();

#pragma unroll
        for (int kk = 0; kk < 16; kk++) {
            float4 a0 = *(const float4*)&As[kk][ty * 8];
            float4 a1 = *(const float4*)&As[kk][ty * 8 + 4];
            float4 b0 = *(const float4*)&Bs[kk][tx * 8];
            float4 b1 = *(const float4*)&Bs[kk][tx * 8 + 4];
            float ar[8] = {a0.x, a0.y, a0.z, a0.w, a1.x, a1.y, a1.z, a1.w};
            float br[8] = {b0.x, b0.y, b0.z, b0.w, b1.x, b1.y, b1.z, b1.w};
#pragma unroll
            for (int i = 0; i < 8; i++)
#pragma unroll
                for (int j = 0; j < 8; j++)
                    acc[i][j] = fmaf(ar[i], br[j], acc[i][j]);
        }
    }

#pragma unroll
    for (int i = 0; i < 8; i++) {
        float4 c0 = make_float4(acc[i][0], acc[i][1], acc[i][2], acc[i][3]);
        float4 c1 = make_float4(acc[i][4], acc[i][5], acc[i][6], acc[i][7]);
        size_t off = (size_t)(m0 + ty * 8 + i) * N + n0 + tx * 8;
        *(float4*)&C[off] = c0;
        *(float4*)&C[off + 4] = c1;
    }
}

// ---------------------------------------------------------------------------
// RoPE in-place on T laid out [S, nheads*HD]; pairs (2i, 2i+1) rotated.
// ---------------------------------------------------------------------------
__global__ void rope_kernel(float* __restrict__ T,
                            const float* __restrict__ cosT,
                            const float* __restrict__ sinT,
                            int nheads, int total)
{
    int idx = blockIdx.x * blockDim.x + threadIdx.x;
    if (idx >= total) return;
    int i = idx & 63;
    int h = (idx >> 6) % nheads;
    int s = idx / (nheads * 64);
    float c  = cosT[s * 64 + i];
    float sn = sinT[s * 64 + i];
    float* p = T + (size_t)s * nheads * HD + h * HD + 2 * i;
    float e = p[0], o = p[1];
    p[0] = e * c - o * sn;
    p[1] = e * sn + o * c;
}

// ---------------------------------------------------------------------------
// Sliding-window causal GQA attention, flash-style online softmax.
// Block = (head h, 64-query tile). 256 threads: 4 threads per query row,
// each owning 32 head dims. K/V staged in 32-row smem tiles.
// Masking: key k valid iff 0 <= q-k < WINDOW. Invalid scores -> -1e30
// with running max initialized to -5e29 so every exp argument stays finite
// (masked probs underflow to exactly 0; no -inf - -inf NaN).
// ---------------------------------------------------------------------------
__global__ __launch_bounds__(256) void attn_kernel(
    const float* __restrict__ Q, const float* __restrict__ K,
    const float* __restrict__ V, float* __restrict__ O)
{
    __shared__ float Ksm[32][HD];
    __shared__ float Vsm[32][HD];

    const int h    = blockIdx.x;
    const int q0   = blockIdx.y * 64;
    const int tid  = threadIdx.x;
    const int lane = tid & 31;
    const int row  = tid >> 2;      // 0..63
    const int p    = tid & 3;       // dim part
    const int q    = q0 + row;
    const int kvh  = h >> 2;        // N_REP = 4
    const float scale = 0.08838834764831845f; // 1/sqrt(128)

    // Q row slice -> registers
    float qreg[32];
    {
        const float4* qp =
            (const float4*)(Q + (size_t)q * (NQ * HD) + h * HD + p * 32);
#pragma unroll
        for (int i = 0; i < 8; i++) {
            float4 v = qp[i];
            qreg[4 * i + 0] = v.x; qreg[4 * i + 1] = v.y;
            qreg[4 * i + 2] = v.z; qreg[4 * i + 3] = v.w;
        }
    }

    float o_acc[32];
#pragma unroll
    for (int d = 0; d < 32; d++) o_acc[d] = 0.f;
    float m = -5e29f, l = 0.f;

    int kv_begin = q0 - WINDOW + 1;
    if (kv_begin < 0) kv_begin = 0;
    kv_begin &= ~31;

    for (int kv0 = kv_begin; kv0 < q0 + 64; kv0 += 32) {
        __syncthreads();
        // stage 32x128 K and V tiles (float4, fully coalesced)
        for (int i = tid; i < 32 * HD / 4; i += 256) {
            int r = i >> 5;
            int c = (i & 31) * 4;
            size_t g = (size_t)(kv0 + r) * (NKV * HD) + kvh * HD + c;
            *(float4*)&Ksm[r][c] = *(const float4*)&K[g];
            *(float4*)&Vsm[r][c] = *(const float4*)&V[g];
        }
        __syncthreads();

        float sp[8];
        float tm = -5e29f;
#pragma unroll 4
        for (int j = 0; j < 32; j++) {
            float s = 0.f;
#pragma unroll
            for (int d = 0; d < 32; d++)
                s = fmaf(qreg[d], Ksm[j][p * 32 + d], s);
            // full 128-dim dot: combine the 4 partial lanes of this row
            s += __shfl_xor_sync(0xffffffffu, s, 1);
            s += __shfl_xor_sync(0xffffffffu, s, 2);
            int dlt = q - (kv0 + j);
            s = (dlt >= 0 && dlt < WINDOW) ? s * scale : -1e30f;
            if ((j & 3) == p) sp[j >> 2] = s;
            tm = fmaxf(tm, s);
        }

        float newm  = fmaxf(m, tm);
        float alpha = __expf(m - newm);
        float psum  = 0.f;
#pragma unroll
        for (int jj = 0; jj < 8; jj++) {
            sp[jj] = __expf(sp[jj] - newm);
            psum += sp[jj];
        }
        psum += __shfl_xor_sync(0xffffffffu, psum, 1);
        psum += __shfl_xor_sync(0xffffffffu, psum, 2);
        l = l * alpha + psum;
#pragma unroll
        for (int d = 0; d < 32; d++) o_acc[d] *= alpha;
        m = newm;

#pragma unroll 4
        for (int j = 0; j < 32; j++) {
            float pj = __shfl_sync(0xffffffffu, sp[j >> 2],
                                   (lane & ~3) | (j & 3));
#pragma unroll
            for (int d = 0; d < 32; d++)
                o_acc[d] = fmaf(pj, Vsm[j][p * 32 + d], o_acc[d]);
        }
    }

    float inv = 1.f / l;
    float4* op = (float4*)(O + (size_t)q * (NQ * HD) + h * HD + p * 32);
#pragma unroll
    for (int i = 0; i < 8; i++)
        op[i] = make_float4(o_acc[4 * i + 0] * inv, o_acc[4 * i + 1] * inv,
                            o_acc[4 * i + 2] * inv, o_acc[4 * i + 3] * inv);
}

// ---------------------------------------------------------------------------
extern "C" void kernel_launch(void* const* d_in, const int* in_sizes, int n_in,
                              void* d_out, int out_size)
{
    const float* x  = (const float*)d_in[0];
    const float* fc = (const float*)d_in[1];
    const float* fs = (const float*)d_in[2];
    // d_in[3] = mask (recomputed analytically; unused)
    const float* wq = (const float*)d_in[4];
    const float* wk = (const float*)d_in[5];
    const float* wv = (const float*)d_in[6];
    const float* wo = (const float*)d_in[7];
    float* out = (float*)d_out;

    float *Qb, *Kb, *Vb, *Ab;
    cudaGetSymbolAddress((void**)&Qb, g_Q);
    cudaGetSymbolAddress((void**)&Kb, g_K);
    cudaGetSymbolAddress((void**)&Vb, g_V);
    cudaGetSymbolAddress((void**)&Ab, g_A);

    // QKV projections
    gemm_kernel<<<dim3(D_MODEL / 128, S_LEN / 128), 256>>>(
        x, wq, Qb, S_LEN, NQ * HD, D_MODEL);
    gemm_kernel<<<dim3((NKV * HD) / 128, S_LEN / 128), 256>>>(
        x, wk, Kb, S_LEN, NKV * HD, D_MODEL);
    gemm_kernel<<<dim3((NKV * HD) / 128, S_LEN / 128), 256>>>(
        x, wv, Vb, S_LEN, NKV * HD, D_MODEL);

    // RoPE on Q and K
    {
        int totq = S_LEN * NQ * (HD / 2);
        int totk = S_LEN * NKV * (HD / 2);
        rope_kernel<<<(totq + 255) / 256, 256>>>(Qb, fc, fs, NQ, totq);
        rope_kernel<<<(totk + 255) / 256, 256>>>(Kb, fc, fs, NKV, totk);
    }

    // Sliding-window GQA attention
    attn_kernel<<<dim3(NQ, S_LEN / 64), 256>>>(Qb, Kb, Vb, Ab);

    // Output projection straight into d_out
    gemm_kernel<<<dim3(D_MODEL / 128, S_LEN / 128), 256>>>(
        Ab, wo, out, S_LEN, D_MODEL, D_MODEL);
}

// round 7
// speedup vs baseline: 1.3750x; 1.3750x over previous
#include <cuda_runtime.h>
#include <cuda_bf16.h>
#include <stdint.h>
#include <math.h>

#define S_LEN   2048
#define DM      4096
#define NQ      32
#define NKV     8
#define HD      128
#define WINDOW  1024
#define KDIM    4096
#define NCH     (KDIM / 64)

// ---------------- scratch (__device__ globals; allocation-free rule) -------
__device__ __align__(16) float g_Q[S_LEN * NQ * HD];
__device__ __align__(16) float g_K[S_LEN * NKV * HD];
__device__ __align__(16) float g_V[S_LEN * NKV * HD];
__device__ __align__(16) float g_A[S_LEN * NQ * HD];

__device__ __align__(16) __nv_bfloat16 g_xh[S_LEN * DM],     g_xl[S_LEN * DM];
__device__ __align__(16) __nv_bfloat16 g_wqh[DM * DM],       g_wql[DM * DM];
__device__ __align__(16) __nv_bfloat16 g_wkh[NKV * HD * DM], g_wkl[NKV * HD * DM];
__device__ __align__(16) __nv_bfloat16 g_wvh[NKV * HD * DM], g_wvl[NKV * HD * DM];
__device__ __align__(16) __nv_bfloat16 g_woh[DM * DM],       g_wol[DM * DM];
__device__ __align__(16) __nv_bfloat16 g_ah[S_LEN * DM],     g_al[S_LEN * DM];

// ---------------------------- PTX helpers ----------------------------------
__device__ __forceinline__ uint32_t smem_u32(const void* p) {
    uint32_t a;
    asm("{ .reg .u64 t; cvta.to.shared.u64 t, %1; cvt.u32.u64 %0, t; }"
        : "=r"(a) : "l"(p));
    return a;
}

#define SWZ(x) ((x) ^ (((x) >> 3) & 0x70))

__device__ __forceinline__ void cpasync16(uint32_t sa, const void* g) {
    asm volatile("cp.async.cg.shared.global [%0], [%1], 16;" ::"r"(sa), "l"(g)
                 : "memory");
}

__device__ __forceinline__ void ldsm4(uint32_t* r, uint32_t a) {
    asm volatile(
        "ldmatrix.sync.aligned.m8n8.x4.shared.b16 {%0,%1,%2,%3}, [%4];"
        : "=r"(r[0]), "=r"(r[1]), "=r"(r[2]), "=r"(r[3]) : "r"(a));
}

__device__ __forceinline__ void mma16816(float* d, const uint32_t* a,
                                         const uint32_t* b) {
    asm volatile(
        "mma.sync.aligned.m16n8k16.row.col.f32.bf16.bf16.f32 "
        "{%0,%1,%2,%3},{%4,%5,%6,%7},{%8,%9},{%0,%1,%2,%3};"
        : "+f"(d[0]), "+f"(d[1]), "+f"(d[2]), "+f"(d[3])
        : "r"(a[0]), "r"(a[1]), "r"(a[2]), "r"(a[3]), "r"(b[0]), "r"(b[1]));
}

// ---------------------------------------------------------------------------
// Tensor-core GEMM: C[M,N] = A[M,K] * B^T, B supplied as [N,K] (K-major).
// A,B given as split bf16 (hi/lo); 3 mma terms (hh, hl, lh) recover fp32-ish
// accuracy. 128x128 CTA tile, 8 warps x (32x64), K chunks of 64, double-
// buffered swizzled smem staged with cp.async.
// ---------------------------------------------------------------------------
#define GEMM_SMEM (2 * 4 * 16384)

__global__ __launch_bounds__(256, 1)
void gemm_tc(const __nv_bfloat16* __restrict__ Ah,
             const __nv_bfloat16* __restrict__ Al,
             const __nv_bfloat16* __restrict__ Bh,
             const __nv_bfloat16* __restrict__ Bl,
             float* __restrict__ C, int ldc)
{
    extern __shared__ char smem[];
    const uint32_t sb = smem_u32(smem);
    const int tid  = threadIdx.x;
    const int wid  = tid >> 5;
    const int lane = tid & 31;
    const int m0   = blockIdx.y * 128;
    const int n0   = blockIdx.x * 128;

    const int warp_m = (wid & 3) * 32;
    const int warp_n = (wid >> 2) * 64;

    const __nv_bfloat16* gb[4] = {
        Ah + (size_t)m0 * KDIM, Al + (size_t)m0 * KDIM,
        Bh + (size_t)n0 * KDIM, Bl + (size_t)n0 * KDIM };

    auto stage = [&](int ck, int buf) {
        const uint32_t base = sb + buf * 65536;
#pragma unroll
        for (int j = 0; j < 16; j++) {
            const int i   = tid + j * 256;
            const int a   = i >> 10;
            const int rem = i & 1023;
            const int row = rem >> 3;
            const int c16 = rem & 7;
            cpasync16(base + a * 16384 + SWZ(row * 128 + c16 * 16),
                      gb[a] + (size_t)row * KDIM + ck * 64 + c16 * 8);
        }
        asm volatile("cp.async.commit_group;" ::: "memory");
    };

    float acc[2][8][4];
#pragma unroll
    for (int t = 0; t < 2; t++)
#pragma unroll
        for (int n = 0; n < 8; n++)
#pragma unroll
            for (int j = 0; j < 4; j++) acc[t][n][j] = 0.f;

    // ldmatrix lane->address components
    const int a_row  = warp_m + (lane & 15);         // + t*16
    const int a_half = lane >> 4;                    // 16B half of k16
    const int b_row  = warp_n + ((lane >> 4) & 1) * 8 + (lane & 7); // + p*16
    const int b_half = (lane >> 3) & 1;

    stage(0, 0);

    for (int c = 0; c < NCH; c++) {
        const int buf = c & 1;
        if (c + 1 < NCH) {
            stage(c + 1, buf ^ 1);
            asm volatile("cp.async.wait_group 1;" ::: "memory");
        } else {
            asm volatile("cp.async.wait_group 0;" ::: "memory");
        }
        __syncthreads();

        const uint32_t bAh = sb + buf * 65536;
        const uint32_t bAl = bAh + 16384;
        const uint32_t bBh = bAh + 32768;
        const uint32_t bBl = bAh + 49152;

#pragma unroll
        for (int ks = 0; ks < 4; ks++) {
            uint32_t ah[2][4], al[2][4], bh[4][4], bl[4][4];
#pragma unroll
            for (int t = 0; t < 2; t++) {
                const int r  = a_row + t * 16;
                const uint32_t off =
                    r * 128 + (((ks * 2 + a_half) ^ (r & 7)) * 16);
                ldsm4(ah[t], bAh + off);
                ldsm4(al[t], bAl + off);
            }
#pragma unroll
            for (int p = 0; p < 4; p++) {
                const int r  = b_row + p * 16;
                const uint32_t off =
                    r * 128 + (((ks * 2 + b_half) ^ (r & 7)) * 16);
                ldsm4(bh[p], bBh + off);
                ldsm4(bl[p], bBl + off);
            }
#pragma unroll
            for (int t = 0; t < 2; t++)
#pragma unroll
                for (int n = 0; n < 8; n++) {
                    const uint32_t* bhp = &bh[n >> 1][(n & 1) * 2];
                    const uint32_t* blp = &bl[n >> 1][(n & 1) * 2];
                    mma16816(acc[t][n], ah[t], bhp);
                    mma16816(acc[t][n], ah[t], blp);
                    mma16816(acc[t][n], al[t], bhp);
                }
        }
        __syncthreads();
    }

    // epilogue: frag (g=lane>>2, tg=lane&3): c0,c1 -> row g, c2,c3 -> row g+8
    const int g  = lane >> 2;
    const int tg = lane & 3;
#pragma unroll
    for (int t = 0; t < 2; t++)
#pragma unroll
        for (int n = 0; n < 8; n++) {
            const int col = n0 + warp_n + n * 8 + tg * 2;
            float* d0 = C + (size_t)(m0 + warp_m + t * 16 + g) * ldc + col;
            float* d1 = C + (size_t)(m0 + warp_m + t * 16 + g + 8) * ldc + col;
            *(float2*)d0 = make_float2(acc[t][n][0], acc[t][n][1]);
            *(float2*)d1 = make_float2(acc[t][n][2], acc[t][n][3]);
        }
}

// ---------------------------------------------------------------------------
// fp32 -> (hi, lo) bf16 split, elementwise
// ---------------------------------------------------------------------------
__global__ void split_kernel(const float4* __restrict__ in,
                             __nv_bfloat162* __restrict__ hi,
                             __nv_bfloat162* __restrict__ lo, int n4)
{
    int i = blockIdx.x * blockDim.x + threadIdx.x;
    if (i >= n4) return;
    float4 v = in[i];
    __nv_bfloat16 hx = __float2bfloat16(v.x), hy = __float2bfloat16(v.y);
    __nv_bfloat16 hz = __float2bfloat16(v.z), hw = __float2bfloat16(v.w);
    __nv_bfloat16 lx = __float2bfloat16(v.x - __bfloat162float(hx));
    __nv_bfloat16 ly = __float2bfloat16(v.y - __bfloat162float(hy));
    __nv_bfloat16 lz = __float2bfloat16(v.z - __bfloat162float(hz));
    __nv_bfloat16 lw = __float2bfloat16(v.w - __bfloat162float(hw));
    hi[2 * i]     = __halves2bfloat162(hx, hy);
    hi[2 * i + 1] = __halves2bfloat162(hz, hw);
    lo[2 * i]     = __halves2bfloat162(lx, ly);
    lo[2 * i + 1] = __halves2bfloat162(lz, lw);
}

// ---------------------------------------------------------------------------
// W[K,N] fp32 -> W^T hi/lo bf16 [N,K]  (tiled transpose + split)
// ---------------------------------------------------------------------------
__global__ void tsplit_kernel(const float* __restrict__ W,
                              __nv_bfloat16* __restrict__ Th,
                              __nv_bfloat16* __restrict__ Tl, int K, int N)
{
    __shared__ float t[32][33];
    const int n0 = blockIdx.x * 32, k0 = blockIdx.y * 32;
    const int tx = threadIdx.x, ty = threadIdx.y;   // (32, 8)
#pragma unroll
    for (int j = 0; j < 32; j += 8)
        t[ty + j][tx] = W[(size_t)(k0 + ty + j) * N + n0 + tx];
    __syncthreads();
#pragma unroll
    for (int j = 0; j < 32; j += 8) {
        const int r = ty + j;
        float v = t[tx][r];
        __nv_bfloat16 h = __float2bfloat16(v);
        __nv_bfloat16 l = __float2bfloat16(v - __bfloat162float(h));
        Th[(size_t)(n0 + r) * K + k0 + tx] = h;
        Tl[(size_t)(n0 + r) * K + k0 + tx] = l;
    }
}

// ---------------------------------------------------------------------------
// RoPE in-place on T laid out [S, nheads*HD]
// ---------------------------------------------------------------------------
__global__ void rope_kernel(float* __restrict__ T,
                            const float* __restrict__ cosT,
                            const float* __restrict__ sinT,
                            int nheads, int total)
{
    int idx = blockIdx.x * blockDim.x + threadIdx.x;
    if (idx >= total) return;
    int i = idx & 63;
    int h = (idx >> 6) % nheads;
    int s = idx / (nheads * 64);
    float c  = cosT[s * 64 + i];
    float sn = sinT[s * 64 + i];
    float* p = T + (size_t)s * nheads * HD + h * HD + 2 * i;
    float e = p[0], o = p[1];
    p[0] = e * c - o * sn;
    p[1] = e * sn + o * c;
}

// ---------------------------------------------------------------------------
// Sliding-window causal GQA attention (fp32 flash-style)
// ---------------------------------------------------------------------------
__global__ __launch_bounds__(256) void attn_kernel(
    const float* __restrict__ Q, const float* __restrict__ K,
    const float* __restrict__ V, float* __restrict__ O)
{
    __shared__ float Ksm[32][HD];
    __shared__ float Vsm[32][HD];

    const int h    = blockIdx.x;
    const int q0   = blockIdx.y * 64;
    const int tid  = threadIdx.x;
    const int lane = tid & 31;
    const int row  = tid >> 2;
    const int p    = tid & 3;
    const int q    = q0 + row;
    const int kvh  = h >> 2;
    const float scale = 0.08838834764831845f;

    float qreg[32];
    {
        const float4* qp =
            (const float4*)(Q + (size_t)q * (NQ * HD) + h * HD + p * 32);
#pragma unroll
        for (int i = 0; i < 8; i++) {
            float4 v = qp[i];
            qreg[4 * i + 0] = v.x; qreg[4 * i + 1] = v.y;
            qreg[4 * i + 2] = v.z; qreg[4 * i + 3] = v.w;
        }
    }

    float o_acc[32];
#pragma unroll
    for (int d = 0; d < 32; d++) o_acc[d] = 0.f;
    float m = -5e29f, l = 0.f;

    int kv_begin = q0 - WINDOW + 1;
    if (kv_begin < 0) kv_begin = 0;
    kv_begin &= ~31;

    for (int kv0 = kv_begin; kv0 < q0 + 64; kv0 += 32) {
        __syncthreads();
        for (int i = tid; i < 32 * HD / 4; i += 256) {
            int r = i >> 5;
            int c = (i & 31) * 4;
            size_t g = (size_t)(kv0 + r) * (NKV * HD) + kvh * HD + c;
            *(float4*)&Ksm[r][c] = *(const float4*)&K[g];
            *(float4*)&Vsm[r][c] = *(const float4*)&V[g];
        }
        __syncthreads();

        float sp[8];
        float tm = -5e29f;
#pragma unroll 4
        for (int j = 0; j < 32; j++) {
            float s = 0.f;
#pragma unroll
            for (int d = 0; d < 32; d++)
                s = fmaf(qreg[d], Ksm[j][p * 32 + d], s);
            s += __shfl_xor_sync(0xffffffffu, s, 1);
            s += __shfl_xor_sync(0xffffffffu, s, 2);
            int dlt = q - (kv0 + j);
            s = (dlt >= 0 && dlt < WINDOW) ? s * scale : -1e30f;
            if ((j & 3) == p) sp[j >> 2] = s;
            tm = fmaxf(tm, s);
        }

        float newm  = fmaxf(m, tm);
        float alpha = __expf(m - newm);
        float psum  = 0.f;
#pragma unroll
        for (int jj = 0; jj < 8; jj++) {
            sp[jj] = __expf(sp[jj] - newm);
            psum += sp[jj];
        }
        psum += __shfl_xor_sync(0xffffffffu, psum, 1);
        psum += __shfl_xor_sync(0xffffffffu, psum, 2);
        l = l * alpha + psum;
#pragma unroll
        for (int d = 0; d < 32; d++) o_acc[d] *= alpha;
        m = newm;

#pragma unroll 4
        for (int j = 0; j < 32; j++) {
            float pj = __shfl_sync(0xffffffffu, sp[j >> 2],
                                   (lane & ~3) | (j & 3));
#pragma unroll
            for (int d = 0; d < 32; d++)
                o_acc[d] = fmaf(pj, Vsm[j][p * 32 + d], o_acc[d]);
        }
    }

    float inv = 1.f / l;
    float4* op = (float4*)(O + (size_t)q * (NQ * HD) + h * HD + p * 32);
#pragma unroll
    for (int i = 0; i < 8; i++)
        op[i] = make_float4(o_acc[4 * i + 0] * inv, o_acc[4 * i + 1] * inv,
                            o_acc[4 * i + 2] * inv, o_acc[4 * i + 3] * inv);
}

// ---------------------------------------------------------------------------
extern "C" void kernel_launch(void* const* d_in, const int* in_sizes, int n_in,
                              void* d_out, int out_size)
{
    const float* x  = (const float*)d_in[0];
    const float* fc = (const float*)d_in[1];
    const float* fs = (const float*)d_in[2];
    const float* wq = (const float*)d_in[4];
    const float* wk = (const float*)d_in[5];
    const float* wv = (const float*)d_in[6];
    const float* wo = (const float*)d_in[7];
    float* out = (float*)d_out;

    float *Qb, *Kb, *Vb, *Ab;
    cudaGetSymbolAddress((void**)&Qb, g_Q);
    cudaGetSymbolAddress((void**)&Kb, g_K);
    cudaGetSymbolAddress((void**)&Vb, g_V);
    cudaGetSymbolAddress((void**)&Ab, g_A);

    __nv_bfloat16 *xh, *xl, *wqh, *wql, *wkh, *wkl, *wvh, *wvl, *woh, *wol, *ah, *al;
    cudaGetSymbolAddress((void**)&xh,  g_xh);  cudaGetSymbolAddress((void**)&xl,  g_xl);
    cudaGetSymbolAddress((void**)&wqh, g_wqh); cudaGetSymbolAddress((void**)&wql, g_wql);
    cudaGetSymbolAddress((void**)&wkh, g_wkh); cudaGetSymbolAddress((void**)&wkl, g_wkl);
    cudaGetSymbolAddress((void**)&wvh, g_wvh); cudaGetSymbolAddress((void**)&wvl, g_wvl);
    cudaGetSymbolAddress((void**)&woh, g_woh); cudaGetSymbolAddress((void**)&wol, g_wol);
    cudaGetSymbolAddress((void**)&ah,  g_ah);  cudaGetSymbolAddress((void**)&al,  g_al);

    cudaFuncSetAttribute(gemm_tc, cudaFuncAttributeMaxDynamicSharedMemorySize,
                         GEMM_SMEM);

    // ---- split / transpose inputs to bf16 hi/lo ----
    {
        int n4 = S_LEN * DM / 4;
        split_kernel<<<(n4 + 255) / 256, 256>>>((const float4*)x,
            (__nv_bfloat162*)xh, (__nv_bfloat162*)xl, n4);
    }
    tsplit_kernel<<<dim3(DM / 32, DM / 32), dim3(32, 8)>>>(wq, wqh, wql, DM, DM);
    tsplit_kernel<<<dim3((NKV * HD) / 32, DM / 32), dim3(32, 8)>>>(wk, wkh, wkl, DM, NKV * HD);
    tsplit_kernel<<<dim3((NKV * HD) / 32, DM / 32), dim3(32, 8)>>>(wv, wvh, wvl, DM, NKV * HD);
    tsplit_kernel<<<dim3(DM / 32, DM / 32), dim3(32, 8)>>>(wo, woh, wol, DM, DM);

    // ---- projections on tensor cores ----
    gemm_tc<<<dim3(DM / 128, S_LEN / 128), 256, GEMM_SMEM>>>(xh, xl, wqh, wql, Qb, DM);
    gemm_tc<<<dim3((NKV * HD) / 128, S_LEN / 128), 256, GEMM_SMEM>>>(xh, xl, wkh, wkl, Kb, NKV * HD);
    gemm_tc<<<dim3((NKV * HD) / 128, S_LEN / 128), 256, GEMM_SMEM>>>(xh, xl, wvh, wvl, Vb, NKV * HD);

    // ---- RoPE ----
    {
        int totq = S_LEN * NQ * (HD / 2);
        int totk = S_LEN * NKV * (HD / 2);
        rope_kernel<<<(totq + 255) / 256, 256>>>(Qb, fc, fs, NQ, totq);
        rope_kernel<<<(totk + 255) / 256, 256>>>(Kb, fc, fs, NKV, totk);
    }

    // ---- attention (fp32) ----
    attn_kernel<<<dim3(NQ, S_LEN / 64), 256>>>(Qb, Kb, Vb, Ab);

    // ---- split attention output, output projection into d_out ----
    {
        int n4 = S_LEN * DM / 4;
        split_kernel<<<(n4 + 255) / 256, 256>>>((const float4*)Ab,
            (__nv_bfloat162*)ah, (__nv_bfloat162*)al, n4);
    }
    gemm_tc<<<dim3(DM / 128, S_LEN / 128), 256, GEMM_SMEM>>>(ah, al, woh, wol, out, DM);
}